// round 16
// baseline (speedup 1.0000x reference)
#include <cuda_runtime.h>
#include <cuda_bf16.h>
#include <cstdint>

// B=128, N=512, diagonals k=0..509 (offset k+1), len(k)=511-k.
// out = (loss[B], loss[B]).
//
// Contiguous-strip cp.async pipeline: CTA (b, s) owns rows [128s, 128s+128).
// A tile = 8 CONSECUTIVE rows; each row's tail cols [(p+1)&~3, 512) staged to
// smem via cp.async.cg 16B ops -> the CTA's DRAM stream is a dense run of
// consecutive row-tails (no mod-4 interleave gaps). 3-stage ring keeps 2
// tiles in flight. Thread k owns diagonal k: reads buf[rr][k+p+1], i.e.
// base + rr*(W+1) with constant unrolled offsets; consecutive threads ->
// consecutive smem addresses (conflict-free).
#define NN   512
#define W    516        // padded row stride (2064 B, 16B multiple)
#define KD   510
#define TPB  512
#define RSG  4          // contiguous strips per batch
#define SUB  8          // rows per tile
#define NT   16         // tiles per strip
#define NSTG 3          // pipeline stages
#define MAXB 256

__device__ float2 g_part[MAXB * RSG * 512];
__device__ int    g_count[MAXB];     // zero-init; reset by last CTA each replay

__global__ __launch_bounds__(TPB, 4)
void diag_stream(const float* __restrict__ S, float* __restrict__ out,
                 int B, int out_size) {
    __shared__ __align__(16) float buf[NSTG * SUB * W];   // 49.5 KB ring
    const int b    = blockIdx.x;
    const int s    = blockIdx.y;
    const int tid  = threadIdx.x;
    const int lane = tid & 31;
    const int w    = tid >> 5;      // 0..15
    const int wr   = w & 7;         // row-in-tile this warp stages
    const int half = w >> 3;        // chunk-half
    const int k    = tid;           // diagonal owned (k<510 valid)
    const int rbase = 128 * s;      // first row of this strip

    const float* __restrict__ M = S + (size_t)b * NN * NN;
    const uint32_t sbase = (uint32_t)__cvta_generic_to_shared(buf);

    float sk = 0.f, qk = 0.f;

    // ---- stage tile j into ring slot (j % NSTG): rows p = rbase + 8j + 0..7
    auto issue = [&](int j) {
        const int p  = rbase + SUB * j + wr;
        const int a4 = ((p + 1) & ~3) >> 2;               // first 16B chunk
        const float*   row  = M + (size_t)p * NN;
        const uint32_t drow = sbase +
            (uint32_t)(((j % NSTG) * SUB + wr) * W) * 4u;
        #pragma unroll
        for (int i = 0; i < 2; ++i) {
            const int ch = a4 + lane + 32 * (2 * half + i);
            if (ch < NN / 4) {
                const uint32_t dst = drow + (uint32_t)ch * 16u;
                asm volatile("cp.async.cg.shared.global [%0], [%1], 16;"
                             :: "r"(dst), "l"(row + ch * 4) : "memory");
            }
        }
    };

    issue(0);
    asm volatile("cp.async.commit_group;" ::: "memory");
    issue(1);
    asm volatile("cp.async.commit_group;" ::: "memory");

    for (int j = 0; j < NT; ++j) {
        if (j + 2 < NT) {
            issue(j + 2);
            asm volatile("cp.async.commit_group;" ::: "memory");
            asm volatile("cp.async.wait_group 2;" ::: "memory");
        } else if (j + 1 < NT) {
            asm volatile("cp.async.wait_group 1;" ::: "memory");
        } else {
            asm volatile("cp.async.wait_group 0;" ::: "memory");
        }
        __syncthreads();                       // tile j visible to all

        const int p0 = rbase + SUB * j;
        const float* tb = buf + (j % NSTG) * SUB * W + (k + p0 + 1);
        // row rr: col = k + p0 + rr + 1 -> idx = rr*(W+1); valid iff < 512
        const int kv = 511 - p0 - k;           // rr < kv rows valid
        #pragma unroll
        for (int rr = 0; rr < SUB; ++rr) {
            if (rr < kv) {
                float x = tb[rr * (W + 1)];
                sk += x; qk = fmaf(x, x, qk);
            }
        }
        __syncthreads();                       // release ring slot
    }

    // ---- per-(strip,diag) partial
    if (k < KD)
        g_part[(b * RSG + s) * 512 + k] = make_float2(sk, qk);
    __threadfence();
    __syncthreads();

    __shared__ int is_last;
    if (tid == 0) {
        int old = atomicAdd(&g_count[b], 1);
        is_last = (old == RSG - 1);
        if (old == RSG - 1) g_count[b] = 0;    // reset for next graph replay
    }
    __syncthreads();

    if (is_last) {
        float contrib = 0.f;
        if (k < KD) {
            float Ss = 0.f, Qs = 0.f;
            #pragma unroll
            for (int i = 0; i < RSG; ++i) {    // fixed order: deterministic
                float2 v = g_part[(b * RSG + i) * 512 + k];
                Ss += v.x; Qs += v.y;
            }
            const float len = 511.0f - (float)k;
            float mean = Ss / len;
            float var  = fmaxf((Qs - Ss * mean) / (len - 1.0f), 0.0f);
            contrib = sqrtf(var) * len * 0.2f;
        }
        __shared__ float red[TPB];
        red[tid] = contrib;
        __syncthreads();
        #pragma unroll
        for (int st = TPB / 2; st >= 32; st >>= 1) {
            if (tid < st) red[tid] += red[tid + st];
            __syncthreads();
        }
        if (tid < 32) {
            float v = red[tid];
            #pragma unroll
            for (int off = 16; off > 0; off >>= 1)
                v += __shfl_down_sync(0xFFFFFFFFu, v, off);
            if (tid == 0) {
                float loss = v / (float)KD;
                out[b] = loss;
                if (out_size >= 2 * B) out[B + b] = loss;
            }
        }
    }
}

extern "C" void kernel_launch(void* const* d_in, const int* in_sizes, int n_in,
                              void* d_out, int out_size) {
    const float* S = (const float*)d_in[0];
    float* out = (float*)d_out;
    const int B = in_sizes[0] / (NN * NN);
    dim3 grid(B, RSG);                          // x-major: heavy s=0 CTAs first
    diag_stream<<<grid, TPB>>>(S, out, B, out_size);
}